// round 1
// baseline (speedup 1.0000x reference)
#include <cuda_runtime.h>

#define NN 50000
#define DD 128
#define TILE_R 64
#define XS_STRIDE 68

// scratch (no allocation allowed in kernel_launch)
__device__ float g_h[NN * DD];    // h = X @ W for current layer
__device__ float g_acc[NN * DD];  // scatter accumulator
__device__ float g_h1[NN * DD];   // layer-1 output
__device__ int   g_deg[NN];
__device__ float g_dinv[NN];

__global__ void k_deg_init(int n) {
    int i = blockIdx.x * blockDim.x + threadIdx.x;
    if (i < n) g_deg[i] = 1;  // self-loop
}

__global__ void k_deg_count(const int* __restrict__ dst, int e) {
    int i = blockIdx.x * blockDim.x + threadIdx.x;
    if (i < e) atomicAdd(&g_deg[dst[i]], 1);
}

__global__ void k_dinv(int n) {
    int i = blockIdx.x * blockDim.x + threadIdx.x;
    if (i < n) g_dinv[i] = rsqrtf((float)g_deg[i]);
}

// H[row, :] = X[row, :] @ W   (X from external ptr or g_h1)
__global__ void k_gemm(const float* __restrict__ X_ext, const float* __restrict__ W,
                       int n, int use_ext) {
    extern __shared__ float smem[];
    float* Ws = smem;              // 128 x 128
    float* Xs = smem + DD * DD;    // 128 x XS_STRIDE (transposed: Xs[k][r])
    const float* __restrict__ X = use_ext ? X_ext : g_h1;

    int t = threadIdx.x;           // 256 threads
    int row0 = blockIdx.x * TILE_R;

    // load W (row-major), coalesced float4
#pragma unroll
    for (int i = 0; i < 16; i++) {
        int idx = (i * 256 + t) * 4;
        *(float4*)&Ws[idx] = *(const float4*)&W[idx];
    }
    // load X tile transposed (scalar stores, padded stride limits conflicts)
#pragma unroll
    for (int i = 0; i < 32; i++) {
        int idx = i * 256 + t;       // 0..8191
        int r = idx >> 7;            // /128
        int c = idx & 127;
        int grow = row0 + r;
        float v = (grow < n) ? X[grow * DD + c] : 0.f;
        Xs[c * XS_STRIDE + r] = v;
    }
    __syncthreads();

    int ct = t & 15;   // col-thread 0..15 -> 8 cols each
    int rt = t >> 4;   // row-thread 0..15 -> 4 rows each
    int c0 = ct * 8;
    int r0 = rt * 4;

    float acc[4][8];
#pragma unroll
    for (int i = 0; i < 4; i++)
#pragma unroll
        for (int j = 0; j < 8; j++) acc[i][j] = 0.f;

#pragma unroll 4
    for (int k = 0; k < DD; k++) {
        float4 a  = *(float4*)&Xs[k * XS_STRIDE + r0];
        float4 b0 = *(float4*)&Ws[k * DD + c0];
        float4 b1 = *(float4*)&Ws[k * DD + c0 + 4];
        float av[4] = {a.x, a.y, a.z, a.w};
        float bv[8] = {b0.x, b0.y, b0.z, b0.w, b1.x, b1.y, b1.z, b1.w};
#pragma unroll
        for (int i = 0; i < 4; i++)
#pragma unroll
            for (int j = 0; j < 8; j++) acc[i][j] += av[i] * bv[j];
    }

#pragma unroll
    for (int i = 0; i < 4; i++) {
        int grow = row0 + r0 + i;
        if (grow < n) {
            float4 o0 = {acc[i][0], acc[i][1], acc[i][2], acc[i][3]};
            float4 o1 = {acc[i][4], acc[i][5], acc[i][6], acc[i][7]};
            *(float4*)&g_h[grow * DD + c0]     = o0;
            *(float4*)&g_h[grow * DD + c0 + 4] = o1;
        }
    }
}

__global__ void k_zero(int n4) {
    int i = blockIdx.x * blockDim.x + threadIdx.x;
    if (i < n4) {
        float4 z = {0.f, 0.f, 0.f, 0.f};
        ((float4*)g_acc)[i] = z;
    }
}

// one warp per edge: acc[dst] += h[src] * dinv[src]*dinv[dst]
__global__ void k_scatter(const int* __restrict__ src, const int* __restrict__ dst, int e) {
    int w = blockIdx.x * 8 + (threadIdx.x >> 5);
    int lane = threadIdx.x & 31;
    if (w >= e) return;
    int s = src[w];
    int d = dst[w];
    float nrm = g_dinv[s] * g_dinv[d];
    float4 v = *(const float4*)&g_h[s * DD + lane * 4];
    float* o = &g_acc[d * DD + lane * 4];
    atomicAdd(o + 0, v.x * nrm);
    atomicAdd(o + 1, v.y * nrm);
    atomicAdd(o + 2, v.z * nrm);
    atomicAdd(o + 3, v.w * nrm);
}

// out = relu(acc + h*dinv^2 (self-loop) + b); out -> g_h1 or external
__global__ void k_epi(const float* __restrict__ b, float* __restrict__ out_ext,
                      int use_ext, int n) {
    int i = blockIdx.x * blockDim.x + threadIdx.x;  // one float4 each
    if (i >= n * (DD / 4)) return;
    int node = i >> 5;
    int c4 = (i & 31) * 4;
    float di = g_dinv[node];
    float sl = di * di;
    float4 a = *(float4*)&g_acc[node * DD + c4];
    float4 h = *(float4*)&g_h[node * DD + c4];
    float4 bb = *(const float4*)&b[c4];
    float4 r;
    r.x = fmaxf(fmaf(h.x, sl, a.x) + bb.x, 0.f);
    r.y = fmaxf(fmaf(h.y, sl, a.y) + bb.y, 0.f);
    r.z = fmaxf(fmaf(h.z, sl, a.z) + bb.z, 0.f);
    r.w = fmaxf(fmaf(h.w, sl, a.w) + bb.w, 0.f);
    float* outp = use_ext ? out_ext : g_h1;
    *(float4*)&outp[node * DD + c4] = r;
}

extern "C" void kernel_launch(void* const* d_in, const int* in_sizes, int n_in,
                              void* d_out, int out_size) {
    const float* x  = (const float*)d_in[0];
    const int*   ei = (const int*)d_in[1];
    const float* W1 = (const float*)d_in[2];
    const float* b1 = (const float*)d_in[3];
    const float* W2 = (const float*)d_in[4];
    const float* b2 = (const float*)d_in[5];
    float* out = (float*)d_out;

    int n = in_sizes[0] / DD;       // 50000
    int E = in_sizes[1] / 2;        // 600000
    const int* srcp = ei;
    const int* dstp = ei + E;

    const int T = 256;
    int gemm_smem = (DD * DD + DD * XS_STRIDE) * (int)sizeof(float);  // ~98 KB
    cudaFuncSetAttribute(k_gemm, cudaFuncAttributeMaxDynamicSharedMemorySize, gemm_smem);

    int gN   = (n + T - 1) / T;
    int gE   = (E + T - 1) / T;
    int gGem = (n + TILE_R - 1) / TILE_R;
    int n4   = n * (DD / 4);
    int gZ   = (n4 + T - 1) / T;
    int gSc  = (E + 7) / 8;         // 8 warps (edges) per block
    int gEp  = (n4 + T - 1) / T;

    // degree + norm
    k_deg_init<<<gN, T>>>(n);
    k_deg_count<<<gE, T>>>(dstp, E);
    k_dinv<<<gN, T>>>(n);

    // layer 1
    k_gemm<<<gGem, T, gemm_smem>>>(x, W1, n, 1);
    k_zero<<<gZ, T>>>(n4);
    k_scatter<<<gSc, T>>>(srcp, dstp, E);
    k_epi<<<gEp, T>>>(b1, nullptr, 0, n);   // -> g_h1

    // layer 2
    k_gemm<<<gGem, T, gemm_smem>>>(nullptr, W2, n, 0);  // X = g_h1
    k_zero<<<gZ, T>>>(n4);
    k_scatter<<<gSc, T>>>(srcp, dstp, E);
    k_epi<<<gEp, T>>>(b2, out, 1, n);       // -> d_out
}

// round 6
// speedup vs baseline: 2.8077x; 2.8077x over previous
#include <cuda_runtime.h>

#define NN 50000
#define EE 600000
#define DD 128
#define KC 32
#define XSTR 132
#define SCAN_B 1024
#define NBMAX 64

// scratch (no allocation allowed in kernel_launch)
__device__ float g_h[NN * DD];    // h = X @ W for current layer
__device__ float g_h1[NN * DD];   // layer-1 output
__device__ int   g_dege[NN];      // in-degree (edges only)
__device__ float g_dinv[NN];      // rsqrt(deg+1)
__device__ int   g_rs[NN];        // CSR row start
__device__ int   g_cur[NN];       // binning cursor
__device__ int   g_bsum[NBMAX];   // scan block sums
__device__ int   g_csr[EE];       // CSR column (src) ids

__global__ void k_deg_zero(int n) {
    int i = blockIdx.x * blockDim.x + threadIdx.x;
    if (i < n) g_dege[i] = 0;
}

__global__ void k_deg_count(const int* __restrict__ dst, int e) {
    int i = blockIdx.x * blockDim.x + threadIdx.x;
    if (i < e) {
        int d = dst[i];
        if (d >= 0 && d < NN) atomicAdd(&g_dege[d], 1);
    }
}

__global__ void k_dinv(int n) {
    int i = blockIdx.x * blockDim.x + threadIdx.x;
    if (i < n) g_dinv[i] = rsqrtf((float)(g_dege[i] + 1));  // +1 self-loop
}

// 3-phase exclusive scan of g_dege -> g_rs
__global__ void k_scan_blocks(int n) {
    __shared__ int sm[SCAN_B];
    int t = threadIdx.x;
    int i = blockIdx.x * SCAN_B + t;
    int v = (i < n) ? g_dege[i] : 0;
    sm[t] = v;
    __syncthreads();
#pragma unroll
    for (int off = 1; off < SCAN_B; off <<= 1) {
        int x = (t >= off) ? sm[t - off] : 0;
        __syncthreads();
        sm[t] += x;
        __syncthreads();
    }
    if (i < n) g_rs[i] = sm[t] - v;           // exclusive within block
    if (t == SCAN_B - 1 && blockIdx.x < NBMAX) g_bsum[blockIdx.x] = sm[t];
}

__global__ void k_scan_top(int nb) {
    if (threadIdx.x == 0) {
        if (nb > NBMAX) nb = NBMAX;
        int run = 0;
        for (int i = 0; i < nb; i++) { int v = g_bsum[i]; g_bsum[i] = run; run += v; }
    }
}

__global__ void k_scan_add(int n) {
    int i = blockIdx.x * SCAN_B + threadIdx.x;
    if (i < n && blockIdx.x < NBMAX) {
        int r = g_rs[i] + g_bsum[blockIdx.x];
        g_rs[i] = r;
        g_cur[i] = r;
    }
}

__global__ void k_bin(const int* __restrict__ src, const int* __restrict__ dst, int e) {
    int i = blockIdx.x * blockDim.x + threadIdx.x;
    if (i < e) {
        int d = dst[i];
        if (d >= 0 && d < NN) {
            int pos = atomicAdd(&g_cur[d], 1);
            if (pos >= 0 && pos < EE) g_csr[pos] = src[i];
        }
    }
}

// H = X @ W, 128-row tile per block, 8x8 register tile per thread.
__global__ void __launch_bounds__(256, 2)
k_gemm(const float* __restrict__ X_ext, const float* __restrict__ W,
       int n, int use_ext) {
    extern __shared__ float smem[];
    float* Ws = smem;                 // 128 x 128 (row-major, [k][c])
    float* Xs = smem + DD * DD;       // KC x XSTR (transposed: [k_local][r])
    const float* __restrict__ X = use_ext ? X_ext : g_h1;

    int t = threadIdx.x;              // 256 threads
    int row0 = blockIdx.x * 128;

#pragma unroll
    for (int i = 0; i < 16; i++) {
        int idx = i * 256 + t;
        ((float4*)Ws)[idx] = ((const float4*)W)[idx];
    }

    int ct = t & 15;
    int rt = t >> 4;
    int c0 = ct * 8;
    int r0 = rt * 8;

    float acc[8][8];
#pragma unroll
    for (int i = 0; i < 8; i++)
#pragma unroll
        for (int j = 0; j < 8; j++) acc[i][j] = 0.f;

#pragma unroll 1
    for (int kc = 0; kc < DD; kc += KC) {
        if (kc) __syncthreads();
#pragma unroll
        for (int i = 0; i < 4; i++) {
            int idx = i * 256 + t;        // 0..1023 float4s
            int r = idx >> 3;
            int c4 = (idx & 7) * 4;
            int grow = row0 + r;
            float4 v = make_float4(0.f, 0.f, 0.f, 0.f);
            if (grow < n) v = *(const float4*)&X[grow * DD + kc + c4];
            Xs[(c4 + 0) * XSTR + r] = v.x;
            Xs[(c4 + 1) * XSTR + r] = v.y;
            Xs[(c4 + 2) * XSTR + r] = v.z;
            Xs[(c4 + 3) * XSTR + r] = v.w;
        }
        __syncthreads();

#pragma unroll 4
        for (int kl = 0; kl < KC; kl++) {
            float4 a0 = *(float4*)&Xs[kl * XSTR + r0];
            float4 a1 = *(float4*)&Xs[kl * XSTR + r0 + 4];
            float4 b0 = *(float4*)&Ws[(kc + kl) * DD + c0];
            float4 b1 = *(float4*)&Ws[(kc + kl) * DD + c0 + 4];
            float av[8] = {a0.x, a0.y, a0.z, a0.w, a1.x, a1.y, a1.z, a1.w};
            float bv[8] = {b0.x, b0.y, b0.z, b0.w, b1.x, b1.y, b1.z, b1.w};
#pragma unroll
            for (int i = 0; i < 8; i++)
#pragma unroll
                for (int j = 0; j < 8; j++) acc[i][j] += av[i] * bv[j];
        }
    }

#pragma unroll
    for (int i = 0; i < 8; i++) {
        int grow = row0 + r0 + i;
        if (grow < n) {
            float4 o0 = {acc[i][0], acc[i][1], acc[i][2], acc[i][3]};
            float4 o1 = {acc[i][4], acc[i][5], acc[i][6], acc[i][7]};
            *(float4*)&g_h[grow * DD + c0]     = o0;
            *(float4*)&g_h[grow * DD + c0 + 4] = o1;
        }
    }
}

// one warp per dst node: out[d] = relu( sum_{s in N(d)} h[s]*dinv[s]*dinv[d]
//                                      + h[d]*dinv[d]^2 + b )
// use_ext: 1 -> write to out_ext (final output), 0 -> write to g_h1
__global__ void __launch_bounds__(256)
k_gather(const float* __restrict__ b, float* __restrict__ out_ext,
         int use_ext, int n) {
    int w = blockIdx.x * 8 + (threadIdx.x >> 5);
    int lane = threadIdx.x & 31;
    if (w >= n) return;

    int base = g_rs[w];
    int cnt  = g_dege[w];
    float dd = g_dinv[w];

    // self-loop
    float4 hv = *(const float4*)&g_h[w * DD + lane * 4];
    float sl = dd * dd;
    float4 acc = make_float4(hv.x * sl, hv.y * sl, hv.z * sl, hv.w * sl);

    for (int j0 = 0; j0 < cnt; j0 += 32) {
        int jj = j0 + lane;
        int   sj = 0;
        float nj = 0.f;
        if (jj < cnt) {
            sj = g_csr[base + jj];
            nj = g_dinv[sj];
        }
        int m = min(32, cnt - j0);
        for (int j = 0; j < m; j++) {
            int   s  = __shfl_sync(0xffffffffu, sj, j);
            float nr = __shfl_sync(0xffffffffu, nj, j) * dd;
            float4 v = *(const float4*)&g_h[s * DD + lane * 4];
            acc.x += v.x * nr;
            acc.y += v.y * nr;
            acc.z += v.z * nr;
            acc.w += v.w * nr;
        }
    }

    float4 bb = *(const float4*)&b[lane * 4];
    float4 r;
    r.x = fmaxf(acc.x + bb.x, 0.f);
    r.y = fmaxf(acc.y + bb.y, 0.f);
    r.z = fmaxf(acc.z + bb.z, 0.f);
    r.w = fmaxf(acc.w + bb.w, 0.f);
    float* outp = use_ext ? out_ext : g_h1;
    *(float4*)&outp[w * DD + lane * 4] = r;
}

extern "C" void kernel_launch(void* const* d_in, const int* in_sizes, int n_in,
                              void* d_out, int out_size) {
    const float* x  = (const float*)d_in[0];
    const int*   ei = (const int*)d_in[1];
    const float* W1 = (const float*)d_in[2];
    const float* b1 = (const float*)d_in[3];
    const float* W2 = (const float*)d_in[4];
    const float* b2 = (const float*)d_in[5];
    float* out = (float*)d_out;

    int n = in_sizes[0] / DD;       // 50000
    int E = in_sizes[1] / 2;        // 600000
    if (n > NN) n = NN;             // scratch-bound safety (shapes are fixed)
    if (E > EE) E = EE;
    const int* srcp = ei;
    const int* dstp = ei + E;

    const int T = 256;
    int gemm_smem = (DD * DD + KC * XSTR) * (int)sizeof(float);  // ~82.4 KB
    cudaFuncSetAttribute(k_gemm, cudaFuncAttributeMaxDynamicSharedMemorySize, gemm_smem);

    int gN   = (n + T - 1) / T;
    int gE   = (E + T - 1) / T;
    int gGem = (n + 127) / 128;
    int nb   = (n + SCAN_B - 1) / SCAN_B;   // 49
    int gWarp = (n + 7) / 8;                // 8 warps (nodes) per block

    // degree + norm + CSR build
    k_deg_zero<<<gN, T>>>(n);
    k_deg_count<<<gE, T>>>(dstp, E);
    k_dinv<<<gN, T>>>(n);
    k_scan_blocks<<<nb, SCAN_B>>>(n);
    k_scan_top<<<1, 32>>>(nb);
    k_scan_add<<<nb, SCAN_B>>>(n);
    k_bin<<<gE, T>>>(srcp, dstp, E);

    // layer 1
    k_gemm<<<gGem, T, gemm_smem>>>(x, W1, n, 1);
    k_gather<<<gWarp, T>>>(b1, nullptr, 0, n);   // -> g_h1

    // layer 2
    k_gemm<<<gGem, T, gemm_smem>>>(nullptr, W2, n, 0);  // X = g_h1
    k_gather<<<gWarp, T>>>(b2, out, 1, n);       // -> d_out
}

// round 7
// speedup vs baseline: 3.0363x; 1.0814x over previous
#include <cuda_runtime.h>
#include <cstdint>

#define NN 50000
#define EE 600000
#define DD 128
#define SCAN_B 1024
#define NBMAX 64
#define XP 132   // Xs row stride (floats): bank = 4*row+col -> conflict-free A frags
#define WP 136   // Ws row stride (floats): bank = 8*k+col  -> conflict-free B frags

// scratch (no allocation allowed in kernel_launch)
__device__ float g_h[NN * DD];    // h = X @ W for current layer
__device__ float g_h1[NN * DD];   // layer-1 output
__device__ int   g_dege[NN];      // in-degree (edges only)
__device__ float g_dinv[NN];      // rsqrt(deg+1)
__device__ int   g_rs[NN];        // CSR row start
__device__ int   g_cur[NN];       // binning cursor
__device__ int   g_bsum[NBMAX];   // scan block sums
__device__ int   g_csr[EE];       // CSR column (src) ids

__global__ void k_deg_zero(int n) {
    int i = blockIdx.x * blockDim.x + threadIdx.x;
    if (i < n) g_dege[i] = 0;
}

__global__ void k_deg_count(const int* __restrict__ dst, int e) {
    int i = blockIdx.x * blockDim.x + threadIdx.x;
    if (i < e) {
        int d = dst[i];
        if (d >= 0 && d < NN) atomicAdd(&g_dege[d], 1);
    }
}

__global__ void k_dinv(int n) {
    int i = blockIdx.x * blockDim.x + threadIdx.x;
    if (i < n) g_dinv[i] = rsqrtf((float)(g_dege[i] + 1));  // +1 self-loop
}

// 3-phase exclusive scan of g_dege -> g_rs
__global__ void k_scan_blocks(int n) {
    __shared__ int sm[SCAN_B];
    int t = threadIdx.x;
    int i = blockIdx.x * SCAN_B + t;
    int v = (i < n) ? g_dege[i] : 0;
    sm[t] = v;
    __syncthreads();
#pragma unroll
    for (int off = 1; off < SCAN_B; off <<= 1) {
        int x = (t >= off) ? sm[t - off] : 0;
        __syncthreads();
        sm[t] += x;
        __syncthreads();
    }
    if (i < n) g_rs[i] = sm[t] - v;           // exclusive within block
    if (t == SCAN_B - 1 && blockIdx.x < NBMAX) g_bsum[blockIdx.x] = sm[t];
}

__global__ void k_scan_top(int nb) {
    if (threadIdx.x == 0) {
        if (nb > NBMAX) nb = NBMAX;
        int run = 0;
        for (int i = 0; i < nb; i++) { int v = g_bsum[i]; g_bsum[i] = run; run += v; }
    }
}

__global__ void k_scan_add(int n) {
    int i = blockIdx.x * SCAN_B + threadIdx.x;
    if (i < n && blockIdx.x < NBMAX) {
        int r = g_rs[i] + g_bsum[blockIdx.x];
        g_rs[i] = r;
        g_cur[i] = r;
    }
}

__global__ void k_bin(const int* __restrict__ src, const int* __restrict__ dst, int e) {
    int i = blockIdx.x * blockDim.x + threadIdx.x;
    if (i < e) {
        int d = dst[i];
        if (d >= 0 && d < NN) {
            int pos = atomicAdd(&g_cur[d], 1);
            if (pos >= 0 && pos < EE) g_csr[pos] = src[i];
        }
    }
}

// ---- TF32 MMA helpers -------------------------------------------------------

__device__ __forceinline__ void f32_split(float x, uint32_t& hi, uint32_t& lo) {
    uint32_t h;
    asm("cvt.rna.tf32.f32 %0, %1;" : "=r"(h) : "f"(x));
    float l = x - __uint_as_float(h);
    uint32_t lr;
    asm("cvt.rna.tf32.f32 %0, %1;" : "=r"(lr) : "f"(l));
    hi = h; lo = lr;
}

__device__ __forceinline__ void mma_tf32(float* c, const uint32_t* a, const uint32_t* b) {
    asm("mma.sync.aligned.m16n8k8.row.col.f32.tf32.tf32.f32 "
        "{%0,%1,%2,%3}, {%4,%5,%6,%7}, {%8,%9}, {%0,%1,%2,%3};"
        : "+f"(c[0]), "+f"(c[1]), "+f"(c[2]), "+f"(c[3])
        : "r"(a[0]), "r"(a[1]), "r"(a[2]), "r"(a[3]), "r"(b[0]), "r"(b[1]));
}

// ---- H = X @ W via tf32 tensor cores (3xTF32 split for fp32-like accuracy) --
// 128x128 output tile per block, K=128. 8 warps in 4(m) x 2(n), warp tile 32x64.
__global__ void __launch_bounds__(256)
k_gemm(const float* __restrict__ X_ext, const float* __restrict__ W,
       int n, int use_ext) {
    extern __shared__ float smem[];
    float* Xs = smem;               // 128 x XP
    float* Ws = smem + DD * XP;     // 128(k) x WP  [k][n]
    const float* __restrict__ X = use_ext ? X_ext : g_h1;

    int t = threadIdx.x;
    int row0 = blockIdx.x * 128;

    // stage X tile (guarded, zero-fill) and W, float4 coalesced
#pragma unroll
    for (int i = 0; i < 16; i++) {
        int idx = i * 256 + t;          // float4 index in 128x128
        int r  = idx >> 5;              // 32 float4 per row
        int c4 = (idx & 31) * 4;
        int grow = row0 + r;
        float4 v = make_float4(0.f, 0.f, 0.f, 0.f);
        if (grow < n) v = *(const float4*)&X[grow * DD + c4];
        *(float4*)&Xs[r * XP + c4] = v;
    }
#pragma unroll
    for (int i = 0; i < 16; i++) {
        int idx = i * 256 + t;
        int k  = idx >> 5;
        int c4 = (idx & 31) * 4;
        *(float4*)&Ws[k * WP + c4] = *(const float4*)&W[k * DD + c4];
    }
    __syncthreads();

    int lane = t & 31, warp = t >> 5;
    int wm = (warp >> 1) * 32;          // warp m offset (0/32/64/96)
    int wn = (warp & 1) * 64;           // warp n offset (0/64)
    int qr = lane >> 2;                 // 0..7
    int qc = lane & 3;                  // 0..3

    float acc[2][8][4];
#pragma unroll
    for (int i = 0; i < 2; i++)
#pragma unroll
        for (int j = 0; j < 8; j++)
#pragma unroll
            for (int q = 0; q < 4; q++) acc[i][j][q] = 0.f;

#pragma unroll 1
    for (int k0 = 0; k0 < DD; k0 += 8) {
        uint32_t ahi[2][4], alo[2][4];
#pragma unroll
        for (int i = 0; i < 2; i++) {
            int rb = wm + i * 16 + qr;
            float f0 = Xs[rb * XP + k0 + qc];
            float f1 = Xs[(rb + 8) * XP + k0 + qc];
            float f2 = Xs[rb * XP + k0 + qc + 4];
            float f3 = Xs[(rb + 8) * XP + k0 + qc + 4];
            f32_split(f0, ahi[i][0], alo[i][0]);
            f32_split(f1, ahi[i][1], alo[i][1]);
            f32_split(f2, ahi[i][2], alo[i][2]);
            f32_split(f3, ahi[i][3], alo[i][3]);
        }
        uint32_t bhi[8][2], blo[8][2];
#pragma unroll
        for (int j = 0; j < 8; j++) {
            int col = wn + j * 8 + qr;
            float g0 = Ws[(k0 + qc) * WP + col];
            float g1 = Ws[(k0 + qc + 4) * WP + col];
            f32_split(g0, bhi[j][0], blo[j][0]);
            f32_split(g1, bhi[j][1], blo[j][1]);
        }
#pragma unroll
        for (int i = 0; i < 2; i++)
#pragma unroll
            for (int j = 0; j < 8; j++) {
                mma_tf32(acc[i][j], ahi[i], bhi[j]);
                mma_tf32(acc[i][j], alo[i], bhi[j]);
                mma_tf32(acc[i][j], ahi[i], blo[j]);
            }
    }

    // epilogue: C fragment layout -> g_h
#pragma unroll
    for (int i = 0; i < 2; i++) {
        int r0 = row0 + wm + i * 16 + qr;
#pragma unroll
        for (int j = 0; j < 8; j++) {
            int c = wn + j * 8 + 2 * qc;
            if (r0 < n) {
                float2 v = {acc[i][j][0], acc[i][j][1]};
                *(float2*)&g_h[r0 * DD + c] = v;
            }
            if (r0 + 8 < n) {
                float2 v = {acc[i][j][2], acc[i][j][3]};
                *(float2*)&g_h[(r0 + 8) * DD + c] = v;
            }
        }
    }
}

// one warp per dst node: out[d] = relu( sum_{s in N(d)} h[s]*dinv[s]*dinv[d]
//                                      + h[d]*dinv[d]^2 + b )
__global__ void __launch_bounds__(256)
k_gather(const float* __restrict__ b, float* __restrict__ out_ext,
         int use_ext, int n) {
    int w = blockIdx.x * 8 + (threadIdx.x >> 5);
    int lane = threadIdx.x & 31;
    if (w >= n) return;

    int base = g_rs[w];
    int cnt  = g_dege[w];
    float dd = g_dinv[w];

    float4 hv = *(const float4*)&g_h[w * DD + lane * 4];
    float sl = dd * dd;
    float4 acc = make_float4(hv.x * sl, hv.y * sl, hv.z * sl, hv.w * sl);

    for (int j0 = 0; j0 < cnt; j0 += 32) {
        int jj = j0 + lane;
        int   sj = 0;
        float nj = 0.f;
        if (jj < cnt) {
            sj = g_csr[base + jj];
            nj = g_dinv[sj];
        }
        int m = min(32, cnt - j0);
        for (int j = 0; j < m; j++) {
            int   s  = __shfl_sync(0xffffffffu, sj, j);
            float nr = __shfl_sync(0xffffffffu, nj, j) * dd;
            float4 v = *(const float4*)&g_h[s * DD + lane * 4];
            acc.x += v.x * nr;
            acc.y += v.y * nr;
            acc.z += v.z * nr;
            acc.w += v.w * nr;
        }
    }

    float4 bb = *(const float4*)&b[lane * 4];
    float4 r;
    r.x = fmaxf(acc.x + bb.x, 0.f);
    r.y = fmaxf(acc.y + bb.y, 0.f);
    r.z = fmaxf(acc.z + bb.z, 0.f);
    r.w = fmaxf(acc.w + bb.w, 0.f);
    float* outp = use_ext ? out_ext : g_h1;
    *(float4*)&outp[w * DD + lane * 4] = r;
}

extern "C" void kernel_launch(void* const* d_in, const int* in_sizes, int n_in,
                              void* d_out, int out_size) {
    const float* x  = (const float*)d_in[0];
    const int*   ei = (const int*)d_in[1];
    const float* W1 = (const float*)d_in[2];
    const float* b1 = (const float*)d_in[3];
    const float* W2 = (const float*)d_in[4];
    const float* b2 = (const float*)d_in[5];
    float* out = (float*)d_out;

    int n = in_sizes[0] / DD;       // 50000
    int E = in_sizes[1] / 2;        // 600000
    if (n > NN) n = NN;
    if (E > EE) E = EE;
    const int* srcp = ei;
    const int* dstp = ei + E;

    const int T = 256;
    int gemm_smem = (DD * XP + DD * WP) * (int)sizeof(float);  // ~134 KB
    cudaFuncSetAttribute(k_gemm, cudaFuncAttributeMaxDynamicSharedMemorySize, gemm_smem);

    int gN   = (n + T - 1) / T;
    int gE   = (E + T - 1) / T;
    int gGem = (n + 127) / 128;
    int nb   = (n + SCAN_B - 1) / SCAN_B;   // 49
    int gWarp = (n + 7) / 8;

    // degree + norm + CSR build
    k_deg_zero<<<gN, T>>>(n);
    k_deg_count<<<gE, T>>>(dstp, E);
    k_dinv<<<gN, T>>>(n);
    k_scan_blocks<<<nb, SCAN_B>>>(n);
    k_scan_top<<<1, 32>>>(nb);
    k_scan_add<<<nb, SCAN_B>>>(n);
    k_bin<<<gE, T>>>(srcp, dstp, E);

    // layer 1
    k_gemm<<<gGem, T, gemm_smem>>>(x, W1, n, 1);
    k_gather<<<gWarp, T>>>(b1, nullptr, 0, n);   // -> g_h1

    // layer 2
    k_gemm<<<gGem, T, gemm_smem>>>(nullptr, W2, n, 0);  // X = g_h1
    k_gather<<<gWarp, T>>>(b2, out, 1, n);       // -> d_out
}

// round 8
// speedup vs baseline: 3.5702x; 1.1758x over previous
#include <cuda_runtime.h>
#include <cuda_bf16.h>
#include <cstdint>

#define NN 50000
#define EE 600000
#define DD 128
#define SCAN_B 1024
#define NBMAX 64
#define SP 68    // u32 stride for all split tiles: bank = (4*row+k2) -> conflict-free frags

// scratch (no allocation allowed in kernel_launch)
__device__ float g_h[NN * DD];    // h = X @ W for current layer
__device__ float g_h1[NN * DD];   // layer-1 output
__device__ int   g_dege[NN];      // in-degree (edges only)
__device__ float g_dinv[NN];      // rsqrt(deg+1)
__device__ int   g_rs[NN];        // CSR row start
__device__ int   g_cur[NN];       // binning cursor
__device__ int   g_bsum[NBMAX];   // scan block sums
__device__ int   g_csr[EE];       // CSR column (src) ids

__global__ void k_deg_zero(int n) {
    int i = blockIdx.x * blockDim.x + threadIdx.x;
    if (i < n) g_dege[i] = 0;
}

__global__ void k_deg_count(const int* __restrict__ dst, int e) {
    int i = blockIdx.x * blockDim.x + threadIdx.x;
    if (i < e) {
        int d = dst[i];
        if (d >= 0 && d < NN) atomicAdd(&g_dege[d], 1);
    }
}

// 3-phase exclusive scan of g_dege -> g_rs ; also computes g_dinv (fused)
__global__ void k_scan_blocks(int n) {
    __shared__ int sm[SCAN_B];
    int t = threadIdx.x;
    int i = blockIdx.x * SCAN_B + t;
    int v = (i < n) ? g_dege[i] : 0;
    if (i < n) g_dinv[i] = rsqrtf((float)(v + 1));  // +1 self-loop
    sm[t] = v;
    __syncthreads();
#pragma unroll
    for (int off = 1; off < SCAN_B; off <<= 1) {
        int x = (t >= off) ? sm[t - off] : 0;
        __syncthreads();
        sm[t] += x;
        __syncthreads();
    }
    if (i < n) g_rs[i] = sm[t] - v;           // exclusive within block
    if (t == SCAN_B - 1 && blockIdx.x < NBMAX) g_bsum[blockIdx.x] = sm[t];
}

__global__ void k_scan_top(int nb) {
    if (threadIdx.x == 0) {
        if (nb > NBMAX) nb = NBMAX;
        int run = 0;
        for (int i = 0; i < nb; i++) { int v = g_bsum[i]; g_bsum[i] = run; run += v; }
    }
}

__global__ void k_scan_add(int n) {
    int i = blockIdx.x * SCAN_B + threadIdx.x;
    if (i < n && blockIdx.x < NBMAX) {
        int r = g_rs[i] + g_bsum[blockIdx.x];
        g_rs[i] = r;
        g_cur[i] = r;
    }
}

__global__ void k_bin(const int* __restrict__ src, const int* __restrict__ dst, int e) {
    int i = blockIdx.x * blockDim.x + threadIdx.x;
    if (i < e) {
        int d = dst[i];
        if (d >= 0 && d < NN) {
            int pos = atomicAdd(&g_cur[d], 1);
            if (pos >= 0 && pos < EE) g_csr[pos] = src[i];
        }
    }
}

// ---- BF16 split helpers -----------------------------------------------------

__device__ __forceinline__ void bsplit(float x, uint16_t& h, uint16_t& l) {
    __nv_bfloat16 hb = __float2bfloat16_rn(x);
    float r = x - __bfloat162float(hb);
    __nv_bfloat16 lb = __float2bfloat16_rn(r);
    h = *reinterpret_cast<uint16_t*>(&hb);
    l = *reinterpret_cast<uint16_t*>(&lb);
}

__device__ __forceinline__ void bsplit2(float a, float b, uint32_t& hi, uint32_t& lo) {
    uint16_t ha, la, hb, lb;
    bsplit(a, ha, la);
    bsplit(b, hb, lb);
    hi = (uint32_t)ha | ((uint32_t)hb << 16);
    lo = (uint32_t)la | ((uint32_t)lb << 16);
}

__device__ __forceinline__ void mma_bf16(float* c, const uint32_t* a, const uint32_t* b) {
    asm("mma.sync.aligned.m16n8k16.row.col.f32.bf16.bf16.f32 "
        "{%0,%1,%2,%3}, {%4,%5,%6,%7}, {%8,%9}, {%0,%1,%2,%3};"
        : "+f"(c[0]), "+f"(c[1]), "+f"(c[2]), "+f"(c[3])
        : "r"(a[0]), "r"(a[1]), "r"(a[2]), "r"(a[3]), "r"(b[0]), "r"(b[1]));
}

// ---- H = X @ W via bf16 tensor cores, split ONCE at staging -----------------
// 128x128 output tile per block, K=128. 8 warps in 4(m) x 2(n), warp tile 32x64.
// smem: Xh/Xl [128][SP] u32 (bf16x2 along k), Wh/Wl [128 cols][SP] u32.
__global__ void __launch_bounds__(256)
k_gemm(const float* __restrict__ X_ext, const float* __restrict__ W,
       int n, int use_ext) {
    extern __shared__ uint32_t smem[];
    uint32_t* Xh = smem;
    uint32_t* Xl = Xh + DD * SP;
    uint32_t* Wh = Xl + DD * SP;
    uint32_t* Wl = Wh + DD * SP;
    const float* __restrict__ X = use_ext ? X_ext : g_h1;

    int t = threadIdx.x;
    int row0 = blockIdx.x * 128;

    // stage X: pack bf16 pairs along k (contiguous in X), guarded zero-fill
#pragma unroll
    for (int i = 0; i < 16; i++) {
        int idx = i * 256 + t;          // float4 index: 32 per row
        int r  = idx >> 5;
        int c4 = (idx & 31) * 4;
        int k2 = (idx & 31) * 2;
        int grow = row0 + r;
        float4 v = make_float4(0.f, 0.f, 0.f, 0.f);
        if (grow < n) v = *(const float4*)&X[grow * DD + c4];
        uint32_t h0, l0, h1, l1;
        bsplit2(v.x, v.y, h0, l0);
        bsplit2(v.z, v.w, h1, l1);
        Xh[r * SP + k2]     = h0;  Xl[r * SP + k2]     = l0;
        Xh[r * SP + k2 + 1] = h1;  Xl[r * SP + k2 + 1] = l1;
    }
    // stage W transposed: Wh/Wl[col][k2] packs (W[2k2][col], W[2k2+1][col])
#pragma unroll
    for (int i = 0; i < 32; i++) {
        int p  = i * 256 + t;           // pair index: 64 k2 x 128 cols
        int k2 = p >> 7;
        int nc = p & 127;
        float a = W[(2 * k2) * DD + nc];
        float b = W[(2 * k2 + 1) * DD + nc];
        uint32_t h, l;
        bsplit2(a, b, h, l);
        Wh[nc * SP + k2] = h;
        Wl[nc * SP + k2] = l;
    }
    __syncthreads();

    int lane = t & 31, warp = t >> 5;
    int wm = (warp >> 1) * 32;          // warp m offset (0/32/64/96)
    int wn = (warp & 1) * 64;           // warp n offset (0/64)
    int qr = lane >> 2;                 // 0..7
    int qc = lane & 3;                  // 0..3

    float acc[2][8][4];
#pragma unroll
    for (int i = 0; i < 2; i++)
#pragma unroll
        for (int j = 0; j < 8; j++)
#pragma unroll
            for (int q = 0; q < 4; q++) acc[i][j][q] = 0.f;

#pragma unroll 1
    for (int kc = 0; kc < 8; kc++) {    // 8 chunks of k16
        int kb = kc * 8 + qc;           // k2 base for this thread
        uint32_t ahi[2][4], alo[2][4];
#pragma unroll
        for (int i = 0; i < 2; i++) {
            int ra = (wm + i * 16 + qr) * SP;
            int rb = (wm + i * 16 + qr + 8) * SP;
            ahi[i][0] = Xh[ra + kb];     alo[i][0] = Xl[ra + kb];
            ahi[i][1] = Xh[rb + kb];     alo[i][1] = Xl[rb + kb];
            ahi[i][2] = Xh[ra + kb + 4]; alo[i][2] = Xl[ra + kb + 4];
            ahi[i][3] = Xh[rb + kb + 4]; alo[i][3] = Xl[rb + kb + 4];
        }
#pragma unroll
        for (int j = 0; j < 8; j++) {
            int cb = (wn + j * 8 + qr) * SP;
            uint32_t bhi[2], blo[2];
            bhi[0] = Wh[cb + kb];     blo[0] = Wl[cb + kb];
            bhi[1] = Wh[cb + kb + 4]; blo[1] = Wl[cb + kb + 4];
#pragma unroll
            for (int i = 0; i < 2; i++) {
                mma_bf16(acc[i][j], ahi[i], bhi);
                mma_bf16(acc[i][j], alo[i], bhi);
                mma_bf16(acc[i][j], ahi[i], blo);
            }
        }
    }

    // epilogue: C fragment layout -> g_h
#pragma unroll
    for (int i = 0; i < 2; i++) {
        int r0 = row0 + wm + i * 16 + qr;
#pragma unroll
        for (int j = 0; j < 8; j++) {
            int c = wn + j * 8 + 2 * qc;
            if (r0 < n) {
                float2 v = {acc[i][j][0], acc[i][j][1]};
                *(float2*)&g_h[r0 * DD + c] = v;
            }
            if (r0 + 8 < n) {
                float2 v = {acc[i][j][2], acc[i][j][3]};
                *(float2*)&g_h[(r0 + 8) * DD + c] = v;
            }
        }
    }
}

// one warp per dst node: out[d] = relu( sum_{s in N(d)} h[s]*dinv[s]*dinv[d]
//                                      + h[d]*dinv[d]^2 + b )
__global__ void __launch_bounds__(256)
k_gather(const float* __restrict__ b, float* __restrict__ out_ext,
         int use_ext, int n) {
    int w = blockIdx.x * 8 + (threadIdx.x >> 5);
    int lane = threadIdx.x & 31;
    if (w >= n) return;

    int base = g_rs[w];
    int cnt  = g_dege[w];
    float dd = g_dinv[w];

    float4 hv = *(const float4*)&g_h[w * DD + lane * 4];
    float sl = dd * dd;
    float4 acc = make_float4(hv.x * sl, hv.y * sl, hv.z * sl, hv.w * sl);

    for (int j0 = 0; j0 < cnt; j0 += 32) {
        int jj = j0 + lane;
        int   sj = 0;
        float nj = 0.f;
        if (jj < cnt) {
            sj = g_csr[base + jj];
            nj = g_dinv[sj];
        }
        int m = min(32, cnt - j0);
        for (int j = 0; j < m; j++) {
            int   s  = __shfl_sync(0xffffffffu, sj, j);
            float nr = __shfl_sync(0xffffffffu, nj, j) * dd;
            float4 v = *(const float4*)&g_h[s * DD + lane * 4];
            acc.x += v.x * nr;
            acc.y += v.y * nr;
            acc.z += v.z * nr;
            acc.w += v.w * nr;
        }
    }

    float4 bb = *(const float4*)&b[lane * 4];
    float4 r;
    r.x = fmaxf(acc.x + bb.x, 0.f);
    r.y = fmaxf(acc.y + bb.y, 0.f);
    r.z = fmaxf(acc.z + bb.z, 0.f);
    r.w = fmaxf(acc.w + bb.w, 0.f);
    float* outp = use_ext ? out_ext : g_h1;
    *(float4*)&outp[w * DD + lane * 4] = r;
}

extern "C" void kernel_launch(void* const* d_in, const int* in_sizes, int n_in,
                              void* d_out, int out_size) {
    const float* x  = (const float*)d_in[0];
    const int*   ei = (const int*)d_in[1];
    const float* W1 = (const float*)d_in[2];
    const float* b1 = (const float*)d_in[3];
    const float* W2 = (const float*)d_in[4];
    const float* b2 = (const float*)d_in[5];
    float* out = (float*)d_out;

    int n = in_sizes[0] / DD;       // 50000
    int E = in_sizes[1] / 2;        // 600000
    if (n > NN) n = NN;
    if (E > EE) E = EE;
    const int* srcp = ei;
    const int* dstp = ei + E;

    const int T = 256;
    int gemm_smem = 4 * DD * SP * (int)sizeof(uint32_t);  // 139264 B
    cudaFuncSetAttribute(k_gemm, cudaFuncAttributeMaxDynamicSharedMemorySize, gemm_smem);

    int gN   = (n + T - 1) / T;
    int gE   = (E + T - 1) / T;
    int gGem = (n + 127) / 128;
    int nb   = (n + SCAN_B - 1) / SCAN_B;   // 49
    int gWarp = (n + 7) / 8;

    // CSR build prologue (dinv fused into scan_blocks)
    k_deg_zero<<<gN, T>>>(n);               // 1
    k_deg_count<<<gE, T>>>(dstp, E);        // 2
    k_scan_blocks<<<nb, SCAN_B>>>(n);       // 3
    k_scan_top<<<1, 32>>>(nb);              // 4
    k_scan_add<<<nb, SCAN_B>>>(n);          // 5

    // layer 1 (gemm1 is launch #6 -> profiled by ncu -s 5 -c 1)
    k_gemm<<<gGem, T, gemm_smem>>>(x, W1, n, 1);        // 6
    k_bin<<<gE, T>>>(srcp, dstp, E);                    // 7 (before gather1)
    k_gather<<<gWarp, T>>>(b1, nullptr, 0, n);          // 8 -> g_h1

    // layer 2
    k_gemm<<<gGem, T, gemm_smem>>>(nullptr, W2, n, 0);  // 9, X = g_h1
    k_gather<<<gWarp, T>>>(b2, out, 1, n);              // 10 -> d_out
}